// round 10
// baseline (speedup 1.0000x reference)
#include <cuda_runtime.h>
#include <cuda_bf16.h>

#define N 4096
#define THREADS 256
#define PPB 4                      /* pedestrians per block */
#define NBLOCKS (N / PPB)          /* 1024 */
#define QCH 1024                   /* candidates per warp quarter-chunk */
#define ITERS 8                    /* 8 iters x 4 candidates/lane */
#define BUFCAP 32

typedef unsigned long long ull;
#define FULL 0xffffffffu
#define INFBITS 0x7f800000u

__device__ __forceinline__ ull pack2(float lo, float hi) {
    ull r;
    asm("mov.b64 %0, {%1, %2};" : "=l"(r) : "f"(lo), "f"(hi));
    return r;
}
__device__ __forceinline__ void unpack2(ull v, float& lo, float& hi) {
    asm("mov.b64 {%0, %1}, %2;" : "=f"(lo), "=f"(hi) : "l"(v));
}
__device__ __forceinline__ ull add2(ull a, ull b) {
    ull r;
    asm("add.rn.f32x2 %0, %1, %2;" : "=l"(r) : "l"(a), "l"(b));
    return r;
}
__device__ __forceinline__ ull fma2(ull a, ull b, ull c) {
    ull r;
    asm("fma.rn.f32x2 %0, %1, %2, %3;" : "=l"(r) : "l"(a), "l"(b), "l"(c));
    return r;
}

__device__ __forceinline__ unsigned fifth_smallest(float d0, float d1, int lane) {
    // 5th smallest of the warp's retained 64 values (>= chunk true 5th >= global 5th)
    unsigned e0 = __float_as_uint(d0), e1 = __float_as_uint(d1);
    unsigned m = INFBITS;
    #pragma unroll
    for (int r = 0; r < 5; r++) {
        m = __reduce_min_sync(FULL, e0);
        unsigned bal = __ballot_sync(FULL, e0 == m);
        if (lane == __ffs(bal) - 1) { e0 = e1; e1 = INFBITS; }
    }
    return m;
}

__global__ __launch_bounds__(THREADS, 6)
void nn_tag_pool_kernel(const float* __restrict__ obs1,
                        const float* __restrict__ obs2,
                        const float* __restrict__ W,
                        const float* __restrict__ b,
                        float* __restrict__ out)
{
    __shared__ float s_xs[N];           // 16 KB, SoA x
    __shared__ float s_ys[N];           // 16 KB, SoA y
    __shared__ unsigned s_cnt[PPB];
    __shared__ unsigned s_vth[PPB];     // positive-float bits: uint order == float order
    __shared__ ull s_buf[PPB][BUFCAP];

    const int lane = threadIdx.x & 31;
    const int warp = threadIdx.x >> 5;
    const int pair    = warp >> 2;       // 0..1 : which ped-pair of this block
    const int quarter = warp & 3;        // 0..3 : which candidate quarter
    const int i0 = blockIdx.x * PPB + pair * 2;
    const int i1 = i0 + 1;

    if (threadIdx.x < PPB) { s_cnt[threadIdx.x] = 0; s_vth[threadIdx.x] = INFBITS; }

    // ---- Stage obs2 into SoA smem (register-adjacent pairs for f32x2 math).
    const float2* __restrict__ pos2 = (const float2*)obs2;
    #pragma unroll 4
    for (int j = threadIdx.x; j < N; j += THREADS) {
        float2 p = __ldg(&pos2[j]);
        s_xs[j] = p.x; s_ys[j] = p.y;
    }
    __syncthreads();

    const float2 pa = __ldg(&pos2[i0]);
    const float2 pb = __ldg(&pos2[i1]);

    const ull ones = pack2(1.0f, 1.0f);
    const ull nax = pack2(-pa.x, -pa.x), nay = pack2(-pa.y, -pa.y);
    const ull nbx = pack2(-pb.x, -pb.x), nby = pack2(-pb.y, -pb.y);

    const float INF = __int_as_float(INFBITS);
    float a0 = INF, a1 = INF;   // ped A per-lane top-2 (self included, dd==1.0 min)
    float b0 = INF, b1 = INF;   // ped B

    const int base4 = quarter * (QCH / 4) + lane;   // float4 index in SoA

    // ---- Phase 1: packed distance scan; exact per-lane keep-2 over 32 cands.
    // Same retention semantics as the validated R5/R9 filter (true 2-smallest).
    #pragma unroll 4
    for (int t = 0; t < ITERS; t++) {
        const float4 x = *(const float4*)&s_xs[(base4 + t * 32) * 4];
        const float4 y = *(const float4*)&s_ys[(base4 + t * 32) * 4];
        const ull xlo = pack2(x.x, x.y), xhi = pack2(x.z, x.w);   // adjacent: free
        const ull ylo = pack2(y.x, y.y), yhi = pack2(y.z, y.w);
        // ped A: 4 distances in two packed streams
        {   ull dxl = add2(xlo, nax), dxh = add2(xhi, nax);
            ull dyl = add2(ylo, nay), dyh = add2(yhi, nay);
            ull tl = fma2(dxl, dxl, fma2(dyl, dyl, ones));
            ull th = fma2(dxh, dxh, fma2(dyh, dyh, ones));
            float ta, tb, tc, td; unpack2(tl, ta, tb); unpack2(th, tc, td);
            float lo1 = fminf(ta, tb), hi1 = fmaxf(ta, tb);
            float lo2 = fminf(tc, td), hi2 = fmaxf(tc, td);
            float lo  = fminf(lo1, lo2);                              // min of 4
            float sec = fminf(fmaxf(lo1, lo2), fminf(hi1, hi2));      // 2nd of 4
            float m = fmaxf(a0, lo);
            a0 = fminf(a0, lo);
            a1 = fminf(fminf(a1, sec), m); }    // 2nd of {a0,a1,lo,sec}
        // ped B
        {   ull dxl = add2(xlo, nbx), dxh = add2(xhi, nbx);
            ull dyl = add2(ylo, nby), dyh = add2(yhi, nby);
            ull tl = fma2(dxl, dxl, fma2(dyl, dyl, ones));
            ull th = fma2(dxh, dxh, fma2(dyh, dyh, ones));
            float ta, tb, tc, td; unpack2(tl, ta, tb); unpack2(th, tc, td);
            float lo1 = fminf(ta, tb), hi1 = fmaxf(ta, tb);
            float lo2 = fminf(tc, td), hi2 = fmaxf(tc, td);
            float lo  = fminf(lo1, lo2);
            float sec = fminf(fmaxf(lo1, lo2), fminf(hi1, hi2));
            float m = fmaxf(b0, lo);
            b0 = fminf(b0, lo);
            b1 = fminf(fminf(b1, sec), m); }
    }

    // ---- Phase 2: per-chunk retained-5th; combine via atomicMin.
    // vth >= global 5th-smallest (incl. self): exhaustive filter for top-4 + self.
    unsigned vA = fifth_smallest(a0, a1, lane);
    unsigned vB = fifth_smallest(b0, b1, lane);
    if (lane == 0) {
        atomicMin(&s_vth[pair * 2 + 0], vA);
        atomicMin(&s_vth[pair * 2 + 1], vB);
    }
    __syncthreads();
    const float vthA = __uint_as_float(s_vth[pair * 2 + 0]);
    const float vthB = __uint_as_float(s_vth[pair * 2 + 1]);

    // ---- Phase 3: packed rescan; vote-gated rare append of (distbits, idx).
    #pragma unroll 4
    for (int t = 0; t < ITERS; t++) {
        const float4 x = *(const float4*)&s_xs[(base4 + t * 32) * 4];
        const float4 y = *(const float4*)&s_ys[(base4 + t * 32) * 4];
        const ull xlo = pack2(x.x, x.y), xhi = pack2(x.z, x.w);
        const ull ylo = pack2(y.x, y.y), yhi = pack2(y.z, y.w);
        const unsigned j0 = (unsigned)((base4 + t * 32) * 4);
        {   ull dxl = add2(xlo, nax), dxh = add2(xhi, nax);
            ull dyl = add2(ylo, nay), dyh = add2(yhi, nay);
            ull tl = fma2(dxl, dxl, fma2(dyl, dyl, ones));
            ull th = fma2(dxh, dxh, fma2(dyh, dyh, ones));
            float ta, tb, tc, td; unpack2(tl, ta, tb); unpack2(th, tc, td);
            float gm = fminf(fminf(ta, tb), fminf(tc, td));
            if (__any_sync(FULL, gm <= vthA)) {      // warp-uniform, rare
                if (ta <= vthA) {
                    unsigned s = atomicAdd(&s_cnt[pair * 2 + 0], 1u);
                    if (s < BUFCAP) s_buf[pair * 2 + 0][s] = (((ull)__float_as_uint(ta)) << 32) | j0;
                }
                if (tb <= vthA) {
                    unsigned s = atomicAdd(&s_cnt[pair * 2 + 0], 1u);
                    if (s < BUFCAP) s_buf[pair * 2 + 0][s] = (((ull)__float_as_uint(tb)) << 32) | (j0 + 1);
                }
                if (tc <= vthA) {
                    unsigned s = atomicAdd(&s_cnt[pair * 2 + 0], 1u);
                    if (s < BUFCAP) s_buf[pair * 2 + 0][s] = (((ull)__float_as_uint(tc)) << 32) | (j0 + 2);
                }
                if (td <= vthA) {
                    unsigned s = atomicAdd(&s_cnt[pair * 2 + 0], 1u);
                    if (s < BUFCAP) s_buf[pair * 2 + 0][s] = (((ull)__float_as_uint(td)) << 32) | (j0 + 3);
                }
            } }
        {   ull dxl = add2(xlo, nbx), dxh = add2(xhi, nbx);
            ull dyl = add2(ylo, nby), dyh = add2(yhi, nby);
            ull tl = fma2(dxl, dxl, fma2(dyl, dyl, ones));
            ull th = fma2(dxh, dxh, fma2(dyh, dyh, ones));
            float ta, tb, tc, td; unpack2(tl, ta, tb); unpack2(th, tc, td);
            float gm = fminf(fminf(ta, tb), fminf(tc, td));
            if (__any_sync(FULL, gm <= vthB)) {
                if (ta <= vthB) {
                    unsigned s = atomicAdd(&s_cnt[pair * 2 + 1], 1u);
                    if (s < BUFCAP) s_buf[pair * 2 + 1][s] = (((ull)__float_as_uint(ta)) << 32) | j0;
                }
                if (tb <= vthB) {
                    unsigned s = atomicAdd(&s_cnt[pair * 2 + 1], 1u);
                    if (s < BUFCAP) s_buf[pair * 2 + 1][s] = (((ull)__float_as_uint(tb)) << 32) | (j0 + 1);
                }
                if (tc <= vthB) {
                    unsigned s = atomicAdd(&s_cnt[pair * 2 + 1], 1u);
                    if (s < BUFCAP) s_buf[pair * 2 + 1][s] = (((ull)__float_as_uint(tc)) << 32) | (j0 + 2);
                }
                if (td <= vthB) {
                    unsigned s = atomicAdd(&s_cnt[pair * 2 + 1], 1u);
                    if (s < BUFCAP) s_buf[pair * 2 + 1][s] = (((ull)__float_as_uint(td)) << 32) | (j0 + 3);
                }
            } }
    }
    __syncthreads();

    // ---- Phase 4 + epilogue: warps 0..3 each finish one pedestrian.
    if (warp < PPB) {
        const int ip = blockIdx.x * PPB + warp;
        unsigned n = s_cnt[warp]; if (n > BUFCAP) n = BUFCAP;
        unsigned db = FULL, ji = FULL;
        if ((unsigned)lane < n) {
            ull k = s_buf[warp][lane];
            db = (unsigned)(k >> 32);
            ji = (unsigned)k;
        }
        // exclude self: its distance is bit-exactly 1.0f
        if (db == 0x3f800000u && ji == (unsigned)ip) db = FULL;

        const int kk = lane >> 3;   // neighbor rank for this lane
        const int o  = lane & 7;    // output channel for this lane
        unsigned nb = 0;
        #pragma unroll
        for (int r = 0; r < 4; r++) {
            unsigned md = __reduce_min_sync(FULL, db);
            unsigned ci = (db == md) ? ji : FULL;
            unsigned mi = __reduce_min_sync(FULL, ci);   // lower-index tie-break
            if (kk == r) nb = mi;
            if (db == md && ji == mi) db = FULL;         // pop exactly one entry
        }
        nb &= (N - 1);   // memory safety (only reachable on overflow)

        const float2* __restrict__ o1 = (const float2*)obs1;
        const float2 pp = __ldg(&pos2[ip]);
        const float2 pn = __ldg(&pos2[nb]);
        const float2 qi = __ldg(&o1[ip]);
        const float2 qn = __ldg(&o1[nb]);
        const float px = pn.x - pp.x;
        const float py = pn.y - pp.y;
        const float vx = (pn.x - qn.x) - (pp.x - qi.x);
        const float vy = (pn.y - qn.y) - (pp.y - qi.y);

        const float w0 = __ldg(&W[o * 6 + 0]);
        const float w1 = __ldg(&W[o * 6 + 1]);
        const float w2 = __ldg(&W[o * 6 + 2]);
        const float w3 = __ldg(&W[o * 6 + 3]);
        const float w4 = __ldg(&W[o * 6 + 4]);
        const float w5 = __ldg(&W[o * 6 + 5]);

        float e = __ldg(&b[o]) + w2 + w5 + w0 * px + w1 * py + w3 * vx + w4 * vy;
        out[ip * 32 + lane] = fmaxf(e, 0.0f);   // coalesced 128B store per warp
    }
}

extern "C" void kernel_launch(void* const* d_in, const int* in_sizes, int n_in,
                              void* d_out, int out_size)
{
    const float* obs1 = (const float*)d_in[0];
    const float* obs2 = (const float*)d_in[1];
    const float* W    = (const float*)d_in[2];
    const float* b    = (const float*)d_in[3];
    float* out = (float*)d_out;

    nn_tag_pool_kernel<<<NBLOCKS, THREADS>>>(obs1, obs2, W, b, out);
}

// round 11
// speedup vs baseline: 1.0019x; 1.0019x over previous
#include <cuda_runtime.h>
#include <cuda_bf16.h>

#define N 4096
#define THREADS 256
#define PPB 4                      /* pedestrians per block */
#define NBLOCKS (N / PPB)          /* 1024 */
#define ITERS 8                    /* per warp: 8 iters x 4 candidates/lane */
#define GROUPS 4                   /* phase-3 gate granularity: 2 iters */
#define BUFCAP 32

typedef unsigned long long ull;
#define FULL 0xffffffffu
#define INFBITS 0x7f800000u

__device__ __forceinline__ ull pack2(float lo, float hi) {
    ull r;
    asm("mov.b64 %0, {%1, %2};" : "=l"(r) : "f"(lo), "f"(hi));
    return r;
}
__device__ __forceinline__ void unpack2(ull v, float& lo, float& hi) {
    asm("mov.b64 {%0, %1}, %2;" : "=f"(lo), "=f"(hi) : "l"(v));
}
__device__ __forceinline__ ull add2(ull a, ull b) {
    ull r;
    asm("add.rn.f32x2 %0, %1, %2;" : "=l"(r) : "l"(a), "l"(b));
    return r;
}
__device__ __forceinline__ ull fma2(ull a, ull b, ull c) {
    ull r;
    asm("fma.rn.f32x2 %0, %1, %2, %3;" : "=l"(r) : "l"(a), "l"(b), "l"(c));
    return r;
}

__device__ __forceinline__ unsigned fifth_smallest(float d0, float d1, int lane) {
    // 5th smallest of the warp's retained 64 values (>= chunk true 5th >= global 5th)
    unsigned e0 = __float_as_uint(d0), e1 = __float_as_uint(d1);
    unsigned m = INFBITS;
    #pragma unroll
    for (int r = 0; r < 5; r++) {
        m = __reduce_min_sync(FULL, e0);
        unsigned bal = __ballot_sync(FULL, e0 == m);
        if (lane == __ffs(bal) - 1) { e0 = e1; e1 = INFBITS; }
    }
    return m;
}

__global__ __launch_bounds__(THREADS)
void nn_tag_pool_kernel(const float* __restrict__ obs1,
                        const float* __restrict__ obs2,
                        const float* __restrict__ W,
                        const float* __restrict__ b,
                        float* __restrict__ out)
{
    __shared__ float s_xs[N];           // 16 KB, SoA x
    __shared__ float s_ys[N];           // 16 KB, SoA y
    __shared__ unsigned s_cnt[PPB];
    __shared__ unsigned s_vth[PPB];     // positive-float bits: uint order == float order
    __shared__ ull s_buf[PPB][BUFCAP];

    const int lane = threadIdx.x & 31;
    const int warp = threadIdx.x >> 5;
    const int pair    = warp >> 2;       // 0..1 : which ped-pair of this block
    const int quarter = warp & 3;        // 0..3 : which candidate quarter
    const int i0 = blockIdx.x * PPB + pair * 2;
    const int i1 = i0 + 1;

    if (threadIdx.x < PPB) { s_cnt[threadIdx.x] = 0; s_vth[threadIdx.x] = INFBITS; }

    // ---- Stage obs2 into SoA smem (register-adjacent pairs for f32x2 math).
    const float2* __restrict__ pos2 = (const float2*)obs2;
    #pragma unroll 4
    for (int j = threadIdx.x; j < N; j += THREADS) {
        float2 p = __ldg(&pos2[j]);
        s_xs[j] = p.x; s_ys[j] = p.y;
    }
    __syncthreads();

    const float2 pa = __ldg(&pos2[i0]);
    const float2 pb = __ldg(&pos2[i1]);

    const ull ones = pack2(1.0f, 1.0f);
    const ull nax = pack2(-pa.x, -pa.x), nay = pack2(-pa.y, -pa.y);
    const ull nbx = pack2(-pb.x, -pb.x), nby = pack2(-pb.y, -pb.y);

    const float INF = __int_as_float(INFBITS);
    float a0 = INF, a1 = INF;   // ped A per-lane top-2 (self included, dd==1.0 min)
    float b0 = INF, b1 = INF;   // ped B
    float gmA[GROUPS] = {INF, INF, INF, INF};   // per-lane group minima (gate keys)
    float gmB[GROUPS] = {INF, INF, INF, INF};

    const int base4 = quarter * 256 + lane;   // float4 index in SoA (256 per quarter)

    // ---- Phase 1: packed distance scan; exact per-lane keep-2 over 32 cands.
    // Also records the min of each 2-iteration group for phase-3 gating.
    #pragma unroll
    for (int t = 0; t < ITERS; t++) {
        const float4 x = *(const float4*)&s_xs[(base4 + t * 32) * 4];
        const float4 y = *(const float4*)&s_ys[(base4 + t * 32) * 4];
        const ull xlo = pack2(x.x, x.y), xhi = pack2(x.z, x.w);   // adjacent: free
        const ull ylo = pack2(y.x, y.y), yhi = pack2(y.z, y.w);
        // ped A: 4 distances in two packed streams
        {   ull dxl = add2(xlo, nax), dxh = add2(xhi, nax);
            ull dyl = add2(ylo, nay), dyh = add2(yhi, nay);
            ull tl = fma2(dxl, dxl, fma2(dyl, dyl, ones));
            ull th = fma2(dxh, dxh, fma2(dyh, dyh, ones));
            float ta, tb, tc, td; unpack2(tl, ta, tb); unpack2(th, tc, td);
            float lo1 = fminf(ta, tb), hi1 = fmaxf(ta, tb);
            float lo2 = fminf(tc, td), hi2 = fmaxf(tc, td);
            float lo  = fminf(lo1, lo2);                              // min of 4
            float sec = fminf(fmaxf(lo1, lo2), fminf(hi1, hi2));      // 2nd of 4
            gmA[t >> 1] = fminf(gmA[t >> 1], lo);
            float m = fmaxf(a0, lo);
            a0 = fminf(a0, lo);
            a1 = fminf(fminf(a1, sec), m); }    // 2nd of {a0,a1,lo,sec}
        // ped B
        {   ull dxl = add2(xlo, nbx), dxh = add2(xhi, nbx);
            ull dyl = add2(ylo, nby), dyh = add2(yhi, nby);
            ull tl = fma2(dxl, dxl, fma2(dyl, dyl, ones));
            ull th = fma2(dxh, dxh, fma2(dyh, dyh, ones));
            float ta, tb, tc, td; unpack2(tl, ta, tb); unpack2(th, tc, td);
            float lo1 = fminf(ta, tb), hi1 = fmaxf(ta, tb);
            float lo2 = fminf(tc, td), hi2 = fmaxf(tc, td);
            float lo  = fminf(lo1, lo2);
            float sec = fminf(fmaxf(lo1, lo2), fminf(hi1, hi2));
            gmB[t >> 1] = fminf(gmB[t >> 1], lo);
            float m = fmaxf(b0, lo);
            b0 = fminf(b0, lo);
            b1 = fminf(fminf(b1, sec), m); }
    }

    // ---- Phase 2: per-chunk retained-5th; combine via atomicMin.
    // vth >= global 5th-smallest (incl. self): exhaustive filter for top-4 + self.
    unsigned vA = fifth_smallest(a0, a1, lane);
    unsigned vB = fifth_smallest(b0, b1, lane);
    if (lane == 0) {
        atomicMin(&s_vth[pair * 2 + 0], vA);
        atomicMin(&s_vth[pair * 2 + 1], vB);
    }
    __syncthreads();
    const float vthA = __uint_as_float(s_vth[pair * 2 + 0]);
    const float vthB = __uint_as_float(s_vth[pair * 2 + 1]);

    // ---- Phase 3: gated rescan. A group is recomputed only if some lane's
    // phase-1 group-min admits a candidate (bit-identical math -> exact gate).
    #pragma unroll
    for (int g = 0; g < GROUPS; g++) {
        bool hit = (gmA[g] <= vthA) | (gmB[g] <= vthB);
        if (__any_sync(FULL, hit)) {            // rare, warp-uniform
            #pragma unroll
            for (int tt = 0; tt < 2; tt++) {
                const int t = g * 2 + tt;
                const float4 x = *(const float4*)&s_xs[(base4 + t * 32) * 4];
                const float4 y = *(const float4*)&s_ys[(base4 + t * 32) * 4];
                const ull xlo = pack2(x.x, x.y), xhi = pack2(x.z, x.w);
                const ull ylo = pack2(y.x, y.y), yhi = pack2(y.z, y.w);
                const unsigned j0 = (unsigned)((base4 + t * 32) * 4);
                {   ull dxl = add2(xlo, nax), dxh = add2(xhi, nax);
                    ull dyl = add2(ylo, nay), dyh = add2(yhi, nay);
                    ull tl = fma2(dxl, dxl, fma2(dyl, dyl, ones));
                    ull th = fma2(dxh, dxh, fma2(dyh, dyh, ones));
                    float ta, tb, tc, td; unpack2(tl, ta, tb); unpack2(th, tc, td);
                    if (ta <= vthA) {
                        unsigned s = atomicAdd(&s_cnt[pair * 2 + 0], 1u);
                        if (s < BUFCAP) s_buf[pair * 2 + 0][s] = (((ull)__float_as_uint(ta)) << 32) | j0;
                    }
                    if (tb <= vthA) {
                        unsigned s = atomicAdd(&s_cnt[pair * 2 + 0], 1u);
                        if (s < BUFCAP) s_buf[pair * 2 + 0][s] = (((ull)__float_as_uint(tb)) << 32) | (j0 + 1);
                    }
                    if (tc <= vthA) {
                        unsigned s = atomicAdd(&s_cnt[pair * 2 + 0], 1u);
                        if (s < BUFCAP) s_buf[pair * 2 + 0][s] = (((ull)__float_as_uint(tc)) << 32) | (j0 + 2);
                    }
                    if (td <= vthA) {
                        unsigned s = atomicAdd(&s_cnt[pair * 2 + 0], 1u);
                        if (s < BUFCAP) s_buf[pair * 2 + 0][s] = (((ull)__float_as_uint(td)) << 32) | (j0 + 3);
                    } }
                {   ull dxl = add2(xlo, nbx), dxh = add2(xhi, nbx);
                    ull dyl = add2(ylo, nby), dyh = add2(yhi, nby);
                    ull tl = fma2(dxl, dxl, fma2(dyl, dyl, ones));
                    ull th = fma2(dxh, dxh, fma2(dyh, dyh, ones));
                    float ta, tb, tc, td; unpack2(tl, ta, tb); unpack2(th, tc, td);
                    if (ta <= vthB) {
                        unsigned s = atomicAdd(&s_cnt[pair * 2 + 1], 1u);
                        if (s < BUFCAP) s_buf[pair * 2 + 1][s] = (((ull)__float_as_uint(ta)) << 32) | j0;
                    }
                    if (tb <= vthB) {
                        unsigned s = atomicAdd(&s_cnt[pair * 2 + 1], 1u);
                        if (s < BUFCAP) s_buf[pair * 2 + 1][s] = (((ull)__float_as_uint(tb)) << 32) | (j0 + 1);
                    }
                    if (tc <= vthB) {
                        unsigned s = atomicAdd(&s_cnt[pair * 2 + 1], 1u);
                        if (s < BUFCAP) s_buf[pair * 2 + 1][s] = (((ull)__float_as_uint(tc)) << 32) | (j0 + 2);
                    }
                    if (td <= vthB) {
                        unsigned s = atomicAdd(&s_cnt[pair * 2 + 1], 1u);
                        if (s < BUFCAP) s_buf[pair * 2 + 1][s] = (((ull)__float_as_uint(td)) << 32) | (j0 + 3);
                    } }
            }
        }
    }
    __syncthreads();

    // ---- Phase 4 + epilogue: warps 0..3 each finish one pedestrian.
    if (warp < PPB) {
        const int ip = blockIdx.x * PPB + warp;
        unsigned n = s_cnt[warp]; if (n > BUFCAP) n = BUFCAP;
        unsigned db = FULL, ji = FULL;
        if ((unsigned)lane < n) {
            ull k = s_buf[warp][lane];
            db = (unsigned)(k >> 32);
            ji = (unsigned)k;
        }
        // exclude self: its distance is bit-exactly 1.0f
        if (db == 0x3f800000u && ji == (unsigned)ip) db = FULL;

        const int kk = lane >> 3;   // neighbor rank for this lane
        const int o  = lane & 7;    // output channel for this lane
        unsigned nb = 0;
        #pragma unroll
        for (int r = 0; r < 4; r++) {
            unsigned md = __reduce_min_sync(FULL, db);
            unsigned ci = (db == md) ? ji : FULL;
            unsigned mi = __reduce_min_sync(FULL, ci);   // lower-index tie-break
            if (kk == r) nb = mi;
            if (db == md && ji == mi) db = FULL;         // pop exactly one entry
        }
        nb &= (N - 1);   // memory safety (only reachable on overflow)

        const float2* __restrict__ o1 = (const float2*)obs1;
        const float2 pp = __ldg(&pos2[ip]);
        const float2 pn = __ldg(&pos2[nb]);
        const float2 qi = __ldg(&o1[ip]);
        const float2 qn = __ldg(&o1[nb]);
        const float px = pn.x - pp.x;
        const float py = pn.y - pp.y;
        const float vx = (pn.x - qn.x) - (pp.x - qi.x);
        const float vy = (pn.y - qn.y) - (pp.y - qi.y);

        const float w0 = __ldg(&W[o * 6 + 0]);
        const float w1 = __ldg(&W[o * 6 + 1]);
        const float w2 = __ldg(&W[o * 6 + 2]);
        const float w3 = __ldg(&W[o * 6 + 3]);
        const float w4 = __ldg(&W[o * 6 + 4]);
        const float w5 = __ldg(&W[o * 6 + 5]);

        float e = __ldg(&b[o]) + w2 + w5 + w0 * px + w1 * py + w3 * vx + w4 * vy;
        out[ip * 32 + lane] = fmaxf(e, 0.0f);   // coalesced 128B store per warp
    }
}

extern "C" void kernel_launch(void* const* d_in, const int* in_sizes, int n_in,
                              void* d_out, int out_size)
{
    const float* obs1 = (const float*)d_in[0];
    const float* obs2 = (const float*)d_in[1];
    const float* W    = (const float*)d_in[2];
    const float* b    = (const float*)d_in[3];
    float* out = (float*)d_out;

    nn_tag_pool_kernel<<<NBLOCKS, THREADS>>>(obs1, obs2, W, b, out);
}

// round 12
// speedup vs baseline: 1.0113x; 1.0095x over previous
#include <cuda_runtime.h>
#include <cuda_bf16.h>

#define N 4096
#define THREADS 256
#define PPB 4                      /* pedestrians per block */
#define NBLOCKS (N / PPB)          /* 1024 */
#define ITERS 16                   /* per warp: 16 iters x 2 candidates/lane */
#define BUFCAP 32

typedef unsigned long long ull;
#define FULL 0xffffffffu
#define INFBITS 0x7f800000u

__device__ __forceinline__ ull pack2(float lo, float hi) {
    ull r;
    asm("mov.b64 %0, {%1, %2};" : "=l"(r) : "f"(lo), "f"(hi));
    return r;
}
__device__ __forceinline__ void unpack2(ull v, float& lo, float& hi) {
    asm("mov.b64 {%0, %1}, %2;" : "=f"(lo), "=f"(hi) : "l"(v));
}
__device__ __forceinline__ ull add2(ull a, ull b) {
    ull r;
    asm("add.rn.f32x2 %0, %1, %2;" : "=l"(r) : "l"(a), "l"(b));
    return r;
}
__device__ __forceinline__ ull fma2(ull a, ull b, ull c) {
    ull r;
    asm("fma.rn.f32x2 %0, %1, %2, %3;" : "=l"(r) : "l"(a), "l"(b), "l"(c));
    return r;
}

// dd = (dx*dx + 1) + dy*dy for one candidate; pair (x,y) is register-adjacent.
__device__ __forceinline__ float dist1(ull pxy, ull npi, ull onz) {
    ull d = add2(pxy, npi);          // (dx, dy)
    ull s = fma2(d, d, onz);         // (dx^2+1, dy^2)
    float sx, sy; unpack2(s, sx, sy);
    return sx + sy;
}

__global__ __launch_bounds__(THREADS)
void nn_tag_pool_kernel(const float* __restrict__ obs1,
                        const float* __restrict__ obs2,
                        const float* __restrict__ W,
                        const float* __restrict__ b,
                        float* __restrict__ out)
{
    __shared__ unsigned s_cnt[PPB];
    __shared__ unsigned s_vth[PPB];     // positive-float bits: uint order == float order
    __shared__ ull s_buf[PPB][BUFCAP];

    const int lane = threadIdx.x & 31;
    const int warp = threadIdx.x >> 5;
    const int pair    = warp >> 2;       // 0..1 : which ped-pair of this block
    const int quarter = warp & 3;        // 0..3 : which candidate quarter
    const int i0 = blockIdx.x * PPB + pair * 2;
    const int i1 = i0 + 1;

    if (threadIdx.x < PPB) { s_cnt[threadIdx.x] = 0; s_vth[threadIdx.x] = INFBITS; }
    __syncthreads();

    const float2* __restrict__ pos2 = (const float2*)obs2;
    const float4* __restrict__ pos4 = (const float4*)obs2;
    const float2 pa = __ldg(&pos2[i0]);
    const float2 pb = __ldg(&pos2[i1]);

    const ull onz = pack2(1.0f, 0.0f);
    const ull npA = pack2(-pa.x, -pa.y);
    const ull npB = pack2(-pb.x, -pb.y);

    const float INF = __int_as_float(INFBITS);
    float a0 = INF, a1 = INF;   // ped A per-lane top-2 (self included, dd==1.0 min)
    float b0 = INF, b1 = INF;   // ped B

    const int base4 = quarter * 512 + lane;   // float4 index: 512 per quarter

    // ---- Phase 1: direct-gmem packed scan; exact per-lane keep-2 over 32 cands.
    // Same retention semantics as the validated filter configuration.
    #pragma unroll 8
    for (int t = 0; t < ITERS; t++) {
        const float4 p = __ldg(&pos4[base4 + t * 32]);
        const ull c0 = pack2(p.x, p.y);   // adjacent: free
        const ull c1 = pack2(p.z, p.w);
        {   float ta = dist1(c0, npA, onz);
            float tb = dist1(c1, npA, onz);
            float lo = fminf(ta, tb), hi = fmaxf(ta, tb);
            float m = fmaxf(a0, lo);
            a0 = fminf(a0, lo);
            a1 = fminf(fminf(a1, hi), m); }
        {   float ta = dist1(c0, npB, onz);
            float tb = dist1(c1, npB, onz);
            float lo = fminf(ta, tb), hi = fmaxf(ta, tb);
            float m = fmaxf(b0, lo);
            b0 = fminf(b0, lo);
            b1 = fminf(fminf(b1, hi), m); }
    }

    // ---- Phase 2: retained-5th for A and B, interleaved for latency overlap.
    // vth >= global 5th-smallest (incl. self): exhaustive filter for top-4 + self.
    {
        unsigned eA0 = __float_as_uint(a0), eA1 = __float_as_uint(a1);
        unsigned eB0 = __float_as_uint(b0), eB1 = __float_as_uint(b1);
        unsigned mA = INFBITS, mB = INFBITS;
        #pragma unroll
        for (int r = 0; r < 5; r++) {
            mA = __reduce_min_sync(FULL, eA0);
            mB = __reduce_min_sync(FULL, eB0);
            unsigned balA = __ballot_sync(FULL, eA0 == mA);
            unsigned balB = __ballot_sync(FULL, eB0 == mB);
            if (lane == __ffs(balA) - 1) { eA0 = eA1; eA1 = INFBITS; }
            if (lane == __ffs(balB) - 1) { eB0 = eB1; eB1 = INFBITS; }
        }
        if (lane == 0) {
            atomicMin(&s_vth[pair * 2 + 0], mA);
            atomicMin(&s_vth[pair * 2 + 1], mB);
        }
    }
    __syncthreads();
    const float vthA = __uint_as_float(s_vth[pair * 2 + 0]);
    const float vthB = __uint_as_float(s_vth[pair * 2 + 1]);
    const float vmax = fmaxf(vthA, vthB);

    // ---- Phase 3: rescan (L1-hot); vote-gated rare append of (distbits, idx).
    #pragma unroll 4
    for (int t = 0; t < ITERS; t++) {
        const float4 p = __ldg(&pos4[base4 + t * 32]);
        const ull c0 = pack2(p.x, p.y);
        const ull c1 = pack2(p.z, p.w);
        float tA0 = dist1(c0, npA, onz);
        float tA1 = dist1(c1, npA, onz);
        float tB0 = dist1(c0, npB, onz);
        float tB1 = dist1(c1, npB, onz);
        float gm = fminf(fminf(tA0, tA1), fminf(tB0, tB1));
        if (__any_sync(FULL, gm <= vmax)) {      // warp-uniform, rare
            const unsigned j0 = (unsigned)((base4 + t * 32) * 2);
            if (tA0 <= vthA) {
                unsigned s = atomicAdd(&s_cnt[pair * 2 + 0], 1u);
                if (s < BUFCAP) s_buf[pair * 2 + 0][s] = (((ull)__float_as_uint(tA0)) << 32) | j0;
            }
            if (tA1 <= vthA) {
                unsigned s = atomicAdd(&s_cnt[pair * 2 + 0], 1u);
                if (s < BUFCAP) s_buf[pair * 2 + 0][s] = (((ull)__float_as_uint(tA1)) << 32) | (j0 + 1);
            }
            if (tB0 <= vthB) {
                unsigned s = atomicAdd(&s_cnt[pair * 2 + 1], 1u);
                if (s < BUFCAP) s_buf[pair * 2 + 1][s] = (((ull)__float_as_uint(tB0)) << 32) | j0;
            }
            if (tB1 <= vthB) {
                unsigned s = atomicAdd(&s_cnt[pair * 2 + 1], 1u);
                if (s < BUFCAP) s_buf[pair * 2 + 1][s] = (((ull)__float_as_uint(tB1)) << 32) | (j0 + 1);
            }
        }
    }
    __syncthreads();

    // ---- Phase 4 + epilogue: warps 0..3 each finish one pedestrian.
    if (warp < PPB) {
        const int ip = blockIdx.x * PPB + warp;
        unsigned n = s_cnt[warp]; if (n > BUFCAP) n = BUFCAP;
        unsigned db = FULL, ji = FULL;
        if ((unsigned)lane < n) {
            ull k = s_buf[warp][lane];
            db = (unsigned)(k >> 32);
            ji = (unsigned)k;
        }
        // exclude self: its distance is bit-exactly 1.0f
        if (db == 0x3f800000u && ji == (unsigned)ip) db = FULL;

        const int kk = lane >> 3;   // neighbor rank for this lane
        const int o  = lane & 7;    // output channel for this lane
        unsigned nb = 0;
        #pragma unroll
        for (int r = 0; r < 4; r++) {
            unsigned md = __reduce_min_sync(FULL, db);
            unsigned ci = (db == md) ? ji : FULL;
            unsigned mi = __reduce_min_sync(FULL, ci);   // lower-index tie-break
            if (kk == r) nb = mi;
            if (db == md && ji == mi) db = FULL;         // pop exactly one entry
        }
        nb &= (N - 1);   // memory safety (only reachable on overflow)

        const float2* __restrict__ o1 = (const float2*)obs1;
        const float2 pp = __ldg(&pos2[ip]);
        const float2 pn = __ldg(&pos2[nb]);
        const float2 qi = __ldg(&o1[ip]);
        const float2 qn = __ldg(&o1[nb]);
        const float px = pn.x - pp.x;
        const float py = pn.y - pp.y;
        const float vx = (pn.x - qn.x) - (pp.x - qi.x);
        const float vy = (pn.y - qn.y) - (pp.y - qi.y);

        const float w0 = __ldg(&W[o * 6 + 0]);
        const float w1 = __ldg(&W[o * 6 + 1]);
        const float w2 = __ldg(&W[o * 6 + 2]);
        const float w3 = __ldg(&W[o * 6 + 3]);
        const float w4 = __ldg(&W[o * 6 + 4]);
        const float w5 = __ldg(&W[o * 6 + 5]);

        float e = __ldg(&b[o]) + w2 + w5 + w0 * px + w1 * py + w3 * vx + w4 * vy;
        out[ip * 32 + lane] = fmaxf(e, 0.0f);   // coalesced 128B store per warp
    }
}

extern "C" void kernel_launch(void* const* d_in, const int* in_sizes, int n_in,
                              void* d_out, int out_size)
{
    const float* obs1 = (const float*)d_in[0];
    const float* obs2 = (const float*)d_in[1];
    const float* W    = (const float*)d_in[2];
    const float* b    = (const float*)d_in[3];
    float* out = (float*)d_out;

    nn_tag_pool_kernel<<<NBLOCKS, THREADS>>>(obs1, obs2, W, b, out);
}